// round 9
// baseline (speedup 1.0000x reference)
#include <cuda_runtime.h>
#include <cuda_bf16.h>

#define NV 16384   // 128*128 voxels
#define NT 64      // time samples

// ---------------- device scratch (static, allocation-free) ----------------
__device__ float g_ctcdc[NT * NV];                 // [m][voxel], coalesced
__device__ __align__(16) float g_aifpad[576];      // phys[63+i] = aif_os[i], zero pad
__device__ __align__(16) float g_tsh[512];
__device__ __align__(16) float g_step[512];
__device__ float g_partCdc[64];
__device__ float g_partCnn[3 * 64];
__device__ float g_consts[4];                      // rscale, 2*sp_lam/C_nn[0..2]

// jax.image.resize(method='linear') upsample 64->512: half-pixel centers,
// renormalized (clamped) edges.
__device__ __forceinline__ float interp64(const float* __restrict__ x, int o) {
    float p = (o + 0.5f) * 0.125f - 0.5f;
    if (p <= 0.0f)  return x[0];
    if (p >= 63.0f) return x[63];
    int i = (int)p;              // p > 0 -> trunc == floor
    float f = p - (float)i;
    return (1.0f - f) * x[i] + f * x[i + 1];
}

// ---------------- kernel A: static 1-D tables ----------------
__global__ void k_static(const float* __restrict__ aif, const float* __restrict__ time_) {
    int o = threadIdx.x;                 // 576 threads
    g_aifpad[o] = 0.0f;
    __syncthreads();
    if (o < 512) {
        float ab = (aif[0] + aif[1] + aif[2] + aif[3] + aif[4]) / 5.0f;
        g_aifpad[63 + o] = interp64(aif, o) - ab;
        float t16 = interp64(time_, 16);           // t_os[NEG_SHIFT]
        float tsh = interp64(time_, o) - t16;
        g_tsh[o] = tsh;
        float e = __expf(-500.0f * tsh);
        g_step[o] = __fdividef(1.0f, 1.0f + e);
    }
}

// ---------------- kernel B: per-voxel ctc_dc + partial reductions ----------------
__global__ void k_voxprep(const float* __restrict__ ctc, const float* __restrict__ eta) {
    int v = blockIdx.x * 256 + threadIdx.x;
    float c[NT];
    const float4* p4 = reinterpret_cast<const float4*>(ctc) + (size_t)v * 16;
#pragma unroll
    for (int i = 0; i < 16; ++i) {
        float4 q = p4[i];
        c[4*i+0] = q.x; c[4*i+1] = q.y; c[4*i+2] = q.z; c[4*i+3] = q.w;
    }
    float base = (c[0] + c[1] + c[2] + c[3] + c[4]) / 5.0f;
    float s2;
    {
        float cd = c[0] - base;              // m = 0 : clamped edge sample
        g_ctcdc[v] = cd;
        s2 = cd * cd;
    }
#pragma unroll
    for (int m = 1; m < NT; ++m) {           // interior: 0.4375*c[m-1] + 0.5625*c[m]
        float cd = 0.4375f * c[m-1] + 0.5625f * c[m] - base;
        g_ctcdc[m * NV + v] = cd;
        s2 += cd * cd;
    }
    float e0 = eta[v], e1 = eta[NV + v], e2 = eta[2*NV + v];
    __shared__ float4 sm[256];
    sm[threadIdx.x] = make_float4(s2, e0*e0, e1*e1, e2*e2);
    __syncthreads();
    for (int s = 128; s > 0; s >>= 1) {      // fixed-order tree -> deterministic
        if (threadIdx.x < s) {
            float4 a = sm[threadIdx.x], b = sm[threadIdx.x + s];
            sm[threadIdx.x] = make_float4(a.x+b.x, a.y+b.y, a.z+b.z, a.w+b.w);
        }
        __syncthreads();
    }
    if (threadIdx.x == 0) {
        float4 r = sm[0];
        g_partCdc[blockIdx.x]        = r.x;
        g_partCnn[blockIdx.x]        = r.y;
        g_partCnn[64  + blockIdx.x]  = r.z;
        g_partCnn[128 + blockIdx.x]  = r.w;
    }
}

// ---------------- kernel C: final reduce + constants ----------------
__global__ void k_consts(const float* __restrict__ lam) {
    int t = threadIdx.x;                     // 64 threads
    __shared__ float4 sm[64];
    sm[t] = make_float4(g_partCdc[t], g_partCnn[t], g_partCnn[64 + t], g_partCnn[128 + t]);
    __syncthreads();
    for (int s = 32; s > 0; s >>= 1) {
        if (t < s) {
            float4 a = sm[t], b = sm[t + s];
            sm[t] = make_float4(a.x+b.x, a.y+b.y, a.z+b.z, a.w+b.w);
        }
        __syncthreads();
    }
    if (t == 0) {
        float Cdc = sm[0].x;
        float x = lam[0];
        float sp = fmaxf(x, 0.0f) + log1pf(expf(-fabsf(x)));   // stable softplus
        g_consts[0] = 0.25f / Cdc;             // r[m] = (est/8 - cd) * 2/(8*Cdc)
        g_consts[1] = 2.0f * sp / sm[0].y;
        g_consts[2] = 2.0f * sp / sm[0].z;
        g_consts[3] = 2.0f * sp / sm[0].w;
    }
}

// ---------------- kernel D: 10 GD iterations, one thread per voxel ----------------
__global__ __launch_bounds__(128, 1)
void k_main(const float* __restrict__ eta_in, float* __restrict__ out) {
    __shared__ __align__(16) float s_aif[576];
    __shared__ __align__(16) float s_tsh[512];
    __shared__ __align__(16) float s_step[512];
    __shared__ float s_c[4];
    int tid = threadIdx.x;
    for (int i = tid; i < 576; i += 128) s_aif[i] = g_aifpad[i];
    for (int i = tid; i < 512; i += 128) { s_tsh[i] = g_tsh[i]; s_step[i] = g_step[i]; }
    if (tid < 4) s_c[tid] = g_consts[tid];
    __syncthreads();

    int v = blockIdx.x * 128 + tid;

    float cd[NT];
#pragma unroll
    for (int m = 0; m < NT; ++m) cd[m] = g_ctcdc[m * NV + v];

    float pA = eta_in[v], pk = eta_in[NV + v], pt = eta_in[2*NV + v];
    float A = pA, k = pk, t0 = pt;
    float rscale = s_c[0], rlA = s_c[1], rlk = s_c[2], rlt = s_c[3];

#pragma unroll 1
    for (int it = 0; it < 10; ++it) {
        float acc[NT];
#pragma unroll
        for (int m = 0; m < NT; ++m) acc[m] = 0.0f;

        float kt0 = k * t0;

        // ---------- forward: acc[m] = sum_l ir[l]*aif_os[16+8m-l], l in [16,511] ----------
        // Octet groups g: all octets lb in [16+64g, 16+64g+56] use compile-time
        // m-start M0 = 8g; edge invalidity handled by zero padding of s_aif.
#pragma unroll
        for (int g = 0; g < 8; ++g) {
            const int M0 = 8 * g;
            const int lb0 = 16 + 64 * g;
            const int lb_end = (g == 7) ? 512 : (lb0 + 64);
#pragma unroll 1
            for (int lb = lb0; lb < lb_end; lb += 8) {
                float4 ts0 = *reinterpret_cast<const float4*>(&s_tsh[lb]);
                float4 ts1 = *reinterpret_cast<const float4*>(&s_tsh[lb + 4]);
                float4 st0 = *reinterpret_cast<const float4*>(&s_step[lb]);
                float4 st1 = *reinterpret_cast<const float4*>(&s_step[lb + 4]);
                float tshv[8] = {ts0.x, ts0.y, ts0.z, ts0.w, ts1.x, ts1.y, ts1.z, ts1.w};
                float stv[8]  = {st0.x, st0.y, st0.z, st0.w, st1.x, st1.y, st1.z, st1.w};
                float irv[8];
#pragma unroll
                for (int i = 0; i < 8; ++i) {
                    float x = kt0 - k * tshv[i];
                    float e = __expf(-x);
                    float s = __fdividef(1.0f, 1.0f + e);
                    irv[i] = A * s * stv[i];
                }
                // phys index of aif_os[16+8m-lb-7] is 72+8m-lb ; rebase so offsets >= 0
                const float* ap = s_aif + (72 + 8 * M0 - lb);
#pragma unroll
                for (int m = M0; m < 64; ++m) {
                    float4 a0 = *reinterpret_cast<const float4*>(ap + 8 * (m - M0));
                    float4 a1 = *reinterpret_cast<const float4*>(ap + 8 * (m - M0) + 4);
                    float t = fmaf(irv[7], a0.x, acc[m]);   // a0.x pairs with l = lb+7
                    t = fmaf(irv[6], a0.y, t);
                    t = fmaf(irv[5], a0.z, t);
                    t = fmaf(irv[4], a0.w, t);
                    t = fmaf(irv[3], a1.x, t);
                    t = fmaf(irv[2], a1.y, t);
                    t = fmaf(irv[1], a1.z, t);
                    t = fmaf(irv[0], a1.w, t);
                    acc[m] = t;
                }
            }
        }

        // residual: r[m] = (est/8 - cd) * 0.25/Cdc   (includes the d/d est chain factor)
#pragma unroll
        for (int m = 0; m < NT; ++m)
            acc[m] = (0.125f * acc[m] - cd[m]) * rscale;

        // ---------- adjoint + gradient contraction ----------
        float sumA = 0.0f, sumG = 0.0f, sumGT = 0.0f;
#pragma unroll
        for (int g = 0; g < 8; ++g) {
            const int M0 = 8 * g;
            const int lb0 = 16 + 64 * g;
            const int lb_end = (g == 7) ? 512 : (lb0 + 64);
#pragma unroll 1
            for (int lb = lb0; lb < lb_end; lb += 8) {
                float wv[8] = {0, 0, 0, 0, 0, 0, 0, 0};
                const float* ap = s_aif + (72 + 8 * M0 - lb);
#pragma unroll
                for (int m = M0; m < 64; ++m) {
                    float4 a0 = *reinterpret_cast<const float4*>(ap + 8 * (m - M0));
                    float4 a1 = *reinterpret_cast<const float4*>(ap + 8 * (m - M0) + 4);
                    float rm = acc[m];
                    wv[7] = fmaf(rm, a0.x, wv[7]);
                    wv[6] = fmaf(rm, a0.y, wv[6]);
                    wv[5] = fmaf(rm, a0.z, wv[5]);
                    wv[4] = fmaf(rm, a0.w, wv[4]);
                    wv[3] = fmaf(rm, a1.x, wv[3]);
                    wv[2] = fmaf(rm, a1.y, wv[2]);
                    wv[1] = fmaf(rm, a1.z, wv[1]);
                    wv[0] = fmaf(rm, a1.w, wv[0]);
                }
                float4 ts0 = *reinterpret_cast<const float4*>(&s_tsh[lb]);
                float4 ts1 = *reinterpret_cast<const float4*>(&s_tsh[lb + 4]);
                float4 st0 = *reinterpret_cast<const float4*>(&s_step[lb]);
                float4 st1 = *reinterpret_cast<const float4*>(&s_step[lb + 4]);
                float tshv[8] = {ts0.x, ts0.y, ts0.z, ts0.w, ts1.x, ts1.y, ts1.z, ts1.w};
                float stv[8]  = {st0.x, st0.y, st0.z, st0.w, st1.x, st1.y, st1.z, st1.w};
#pragma unroll
                for (int i = 0; i < 8; ++i) {
                    float tshl = tshv[i];
                    float x = kt0 - k * tshl;
                    float e = __expf(-x);
                    float s = __fdividef(1.0f, 1.0f + e);
                    float u = wv[i] * stv[i];
                    sumA = fmaf(u, s, sumA);                 // dir/dA = s*step
                    float gg = u * A * s * (1.0f - s);       // common factor
                    sumG += gg;
                    sumGT = fmaf(gg, tshl, sumGT);
                }
            }
        }

        // full gradients (dc + reg + positivity) and GD update
        float gA = sumA + rlA * (A - pA) + (A < 0.0f ? 2.0f * A : 0.0f);
        float gk = fmaf(t0, sumG, -sumGT) + rlk * (k - pk) + (k < 0.0f ? 2.0f * k : 0.0f);
        float gt = k * sumG + rlt * (t0 - pt) + (t0 < 0.0f ? 2.0f * t0 : 0.0f);
        A  -= 0.1f * gA;
        k  -= 0.1f * gk;
        t0 -= 0.1f * gt;
    }

    out[v]          = A;
    out[NV + v]     = k;
    out[2*NV + v]   = t0;
}

// ---------------- launch ----------------
extern "C" void kernel_launch(void* const* d_in, const int* in_sizes, int n_in,
                              void* d_out, int out_size) {
    const float* ctc   = (const float*)d_in[0];   // (1,128,128,64)
    const float* aif   = (const float*)d_in[1];   // (1,1,1,64)
    const float* time_ = (const float*)d_in[2];   // (64,)
    // d_in[3] = seg (unused by the reference objective)
    const float* eta   = (const float*)d_in[4];   // (1,3,128,128)
    const float* lam   = (const float*)d_in[5];   // (1,)
    float* out = (float*)d_out;                   // (1,3,128,128)

    k_static <<<1, 576>>>(aif, time_);
    k_voxprep<<<64, 256>>>(ctc, eta);
    k_consts <<<1, 64>>>(lam);
    k_main   <<<128, 128>>>(eta, out);
}

// round 10
// speedup vs baseline: 1.2376x; 1.2376x over previous
#include <cuda_runtime.h>
#include <cuda_bf16.h>

#define NV 16384   // 128*128 voxels
#define NT 64      // time samples
typedef unsigned long long ULL;

// ---------------- device scratch (static, allocation-free) ----------------
__device__ float g_ctcdc[NT * NV];                 // [m][voxel], coalesced
__device__ __align__(16) float g_aifpad[576];      // phys[63+i] = aif_os[i], zero pad
__device__ __align__(16) float g_tsh[512];
__device__ __align__(16) float g_step[512];
__device__ float g_partCdc[64];
__device__ float g_partCnn[3 * 64];
__device__ float g_consts[4];                      // rscale, 2*sp_lam/C_nn[0..2]

// jax.image.resize(method='linear') upsample 64->512: half-pixel centers,
// renormalized (clamped) edges.
__device__ __forceinline__ float interp64(const float* __restrict__ x, int o) {
    float p = (o + 0.5f) * 0.125f - 0.5f;
    if (p <= 0.0f)  return x[0];
    if (p >= 63.0f) return x[63];
    int i = (int)p;              // p > 0 -> trunc == floor
    float f = p - (float)i;
    return (1.0f - f) * x[i] + f * x[i + 1];
}

// ---------------- kernel A: static 1-D tables ----------------
__global__ void k_static(const float* __restrict__ aif, const float* __restrict__ time_) {
    int o = threadIdx.x;                 // 576 threads
    g_aifpad[o] = 0.0f;
    __syncthreads();
    if (o < 512) {
        float ab = (aif[0] + aif[1] + aif[2] + aif[3] + aif[4]) / 5.0f;
        g_aifpad[63 + o] = interp64(aif, o) - ab;
        float t16 = interp64(time_, 16);           // t_os[NEG_SHIFT]
        float tsh = interp64(time_, o) - t16;
        g_tsh[o] = tsh;
        float e = __expf(-500.0f * tsh);
        g_step[o] = __fdividef(1.0f, 1.0f + e);
    }
}

// ---------------- kernel B: per-voxel ctc_dc + partial reductions ----------------
__global__ void k_voxprep(const float* __restrict__ ctc, const float* __restrict__ eta) {
    int v = blockIdx.x * 256 + threadIdx.x;
    float c[NT];
    const float4* p4 = reinterpret_cast<const float4*>(ctc) + (size_t)v * 16;
#pragma unroll
    for (int i = 0; i < 16; ++i) {
        float4 q = p4[i];
        c[4*i+0] = q.x; c[4*i+1] = q.y; c[4*i+2] = q.z; c[4*i+3] = q.w;
    }
    float base = (c[0] + c[1] + c[2] + c[3] + c[4]) / 5.0f;
    float s2;
    {
        float cd = c[0] - base;              // m = 0 : clamped edge sample
        g_ctcdc[v] = cd;
        s2 = cd * cd;
    }
#pragma unroll
    for (int m = 1; m < NT; ++m) {           // interior: 0.4375*c[m-1] + 0.5625*c[m]
        float cd = 0.4375f * c[m-1] + 0.5625f * c[m] - base;
        g_ctcdc[m * NV + v] = cd;
        s2 += cd * cd;
    }
    float e0 = eta[v], e1 = eta[NV + v], e2 = eta[2*NV + v];
    __shared__ float4 sm[256];
    sm[threadIdx.x] = make_float4(s2, e0*e0, e1*e1, e2*e2);
    __syncthreads();
    for (int s = 128; s > 0; s >>= 1) {      // fixed-order tree -> deterministic
        if (threadIdx.x < s) {
            float4 a = sm[threadIdx.x], b = sm[threadIdx.x + s];
            sm[threadIdx.x] = make_float4(a.x+b.x, a.y+b.y, a.z+b.z, a.w+b.w);
        }
        __syncthreads();
    }
    if (threadIdx.x == 0) {
        float4 r = sm[0];
        g_partCdc[blockIdx.x]        = r.x;
        g_partCnn[blockIdx.x]        = r.y;
        g_partCnn[64  + blockIdx.x]  = r.z;
        g_partCnn[128 + blockIdx.x]  = r.w;
    }
}

// ---------------- kernel C: final reduce + constants ----------------
__global__ void k_consts(const float* __restrict__ lam) {
    int t = threadIdx.x;                     // 64 threads
    __shared__ float4 sm[64];
    sm[t] = make_float4(g_partCdc[t], g_partCnn[t], g_partCnn[64 + t], g_partCnn[128 + t]);
    __syncthreads();
    for (int s = 32; s > 0; s >>= 1) {
        if (t < s) {
            float4 a = sm[t], b = sm[t + s];
            sm[t] = make_float4(a.x+b.x, a.y+b.y, a.z+b.z, a.w+b.w);
        }
        __syncthreads();
    }
    if (t == 0) {
        float Cdc = sm[0].x;
        float x = lam[0];
        float sp = fmaxf(x, 0.0f) + log1pf(expf(-fabsf(x)));   // stable softplus
        g_consts[0] = 0.25f / Cdc;             // r[m] = (est/8 - cd) * 2/(8*Cdc)
        g_consts[1] = 2.0f * sp / sm[0].y;
        g_consts[2] = 2.0f * sp / sm[0].z;
        g_consts[3] = 2.0f * sp / sm[0].w;
    }
}

// ---------------- packed fp32x2 helpers (sm_103a) ----------------
__device__ __forceinline__ ULL pack2(float lo, float hi) {
    ULL r; asm("mov.b64 %0, {%1, %2};" : "=l"(r) : "f"(lo), "f"(hi)); return r;
}
__device__ __forceinline__ float2 unpack2(ULL v) {
    float2 r; asm("mov.b64 {%0, %1}, %2;" : "=f"(r.x), "=f"(r.y) : "l"(v)); return r;
}
__device__ __forceinline__ void ffma2(ULL& d, ULL a, ULL b) {
    asm("fma.rn.f32x2 %0, %1, %2, %0;" : "+l"(d) : "l"(a), "l"(b));
}

// ---------------- kernel D: 10 GD iterations, 2 threads per voxel ----------------
// Thread layout: 256 threads/CTA. t0 = tid&127 selects the voxel lane,
// p = tid>>7 selects the octet-parity half of the l-range (warps 0-3: p=0,
// warps 4-7: p=1) so shared-table reads stay warp-uniform (broadcast).
__global__ __launch_bounds__(256, 1)
void k_main(const float* __restrict__ eta_in, float* __restrict__ out) {
    __shared__ __align__(16) float s_aif[576];
    __shared__ __align__(16) float s_tsh[512];
    __shared__ __align__(16) float s_step[512];
    __shared__ float s_ex[128 * 65];     // [t0][m], padded: conflict-free both axes
    __shared__ float s_red[2][128][5];   // partial gradient sums
    __shared__ float s_c[4];
    int tid = threadIdx.x;
    for (int i = tid; i < 576; i += 256) s_aif[i] = g_aifpad[i];
    for (int i = tid; i < 512; i += 256) { s_tsh[i] = g_tsh[i]; s_step[i] = g_step[i]; }
    if (tid < 4) s_c[tid] = g_consts[tid];
    __syncthreads();

    const int t0 = tid & 127;
    const int p  = tid >> 7;
    const int v  = blockIdx.x * 128 + t0;

    float pA = eta_in[v], pk = eta_in[NV + v], pt = eta_in[2*NV + v];
    float A = pA, k = pk, tz = pt;
    const float rscale = s_c[0], rlA = s_c[1], rlk = s_c[2], rlt = s_c[3];

#pragma unroll 1
    for (int it = 0; it < 10; ++it) {
        ULL acc2[NT];
#pragma unroll
        for (int m = 0; m < NT; ++m) acc2[m] = 0ULL;

        float kt0 = k * tz;

        // ---------- forward (my parity's octets): acc[m] = sum_l ir[l]*aif[16+8m-l] ----------
        // Octet lb = 16 + 64g + 8*(2j+p); 1144 m-octet pairs per thread (balanced).
        // f32x2 packs adjacent l's; final acc[m] = lo+hi.
#pragma unroll
        for (int g = 0; g < 8; ++g) {
            const int M0 = 8 * g;
            const int NJ = (g == 7) ? 3 : 4;
#pragma unroll 1
            for (int j = 0; j < NJ; ++j) {
                const int lb = 16 + 64*g + 8*(2*j + p);
                float4 ts0 = *reinterpret_cast<const float4*>(&s_tsh[lb]);
                float4 ts1 = *reinterpret_cast<const float4*>(&s_tsh[lb + 4]);
                float4 st0 = *reinterpret_cast<const float4*>(&s_step[lb]);
                float4 st1 = *reinterpret_cast<const float4*>(&s_step[lb + 4]);
                float tshv[8] = {ts0.x, ts0.y, ts0.z, ts0.w, ts1.x, ts1.y, ts1.z, ts1.w};
                float stv[8]  = {st0.x, st0.y, st0.z, st0.w, st1.x, st1.y, st1.z, st1.w};
                float irv[8];
#pragma unroll
                for (int i = 0; i < 8; ++i) {
                    float x = kt0 - k * tshv[i];
                    float e = __expf(-x);
                    float s = __fdividef(1.0f, 1.0f + e);
                    irv[i] = A * s * stv[i];
                }
                // lane order: aif[p0] pairs with irv[7], aif[p0+1] with irv[6], ...
                ULL I0 = pack2(irv[7], irv[6]);
                ULL I1 = pack2(irv[5], irv[4]);
                ULL I2 = pack2(irv[3], irv[2]);
                ULL I3 = pack2(irv[1], irv[0]);
                const int base = 56 - 16*j - 8*p;   // = 72 + 8*M0 - lb (>=0, 32B aligned)
                const ulonglong2* ap2 = reinterpret_cast<const ulonglong2*>(s_aif + base);
#pragma unroll
                for (int m = M0; m < 64; ++m) {
                    ulonglong2 qa = ap2[2*(m - M0)];
                    ulonglong2 qb = ap2[2*(m - M0) + 1];
                    ffma2(acc2[m], I0, qa.x);
                    ffma2(acc2[m], I1, qa.y);
                    ffma2(acc2[m], I2, qb.x);
                    ffma2(acc2[m], I3, qb.y);
                }
            }
        }

        // ---------- cross-part combine + residual ----------
        if (p == 0) {
#pragma unroll
            for (int m = 0; m < NT; ++m) {
                float2 u = unpack2(acc2[m]);
                s_ex[t0*65 + m] = u.x + u.y;
            }
        }
        __syncthreads();
        if (p == 1) {
#pragma unroll
            for (int m = 0; m < NT; ++m) {
                float2 u = unpack2(acc2[m]);
                float full = u.x + u.y + s_ex[t0*65 + m];
                float cd = __ldg(&g_ctcdc[m * NV + v]);    // L1-resident after iter 1
                s_ex[t0*65 + m] = (0.125f * full - cd) * rscale;
            }
        }
        __syncthreads();

        // ---------- adjoint + gradient contraction (my parity's octets) ----------
        float sumA = 0.0f, sumG = 0.0f, sumGT = 0.0f;
#pragma unroll
        for (int g = 0; g < 8; ++g) {
            const int M0 = 8 * g;
            const int NJ = (g == 7) ? 3 : 4;
#pragma unroll 1
            for (int j = 0; j < NJ; ++j) {
                const int lb = 16 + 64*g + 8*(2*j + p);
                ULL w0 = 0, w1 = 0, w2 = 0, w3 = 0;
                const int base = 56 - 16*j - 8*p;
                const ulonglong2* ap2 = reinterpret_cast<const ulonglong2*>(s_aif + base);
#pragma unroll
                for (int m = M0; m < 64; ++m) {
                    float rm = s_ex[t0*65 + m];
                    ULL rm2 = pack2(rm, rm);
                    ulonglong2 qa = ap2[2*(m - M0)];
                    ulonglong2 qb = ap2[2*(m - M0) + 1];
                    ffma2(w0, rm2, qa.x);
                    ffma2(w1, rm2, qa.y);
                    ffma2(w2, rm2, qb.x);
                    ffma2(w3, rm2, qb.y);
                }
                float2 u0 = unpack2(w0), u1 = unpack2(w1), u2 = unpack2(w2), u3 = unpack2(w3);
                float wv[8] = {u3.y, u3.x, u2.y, u2.x, u1.y, u1.x, u0.y, u0.x};
                float4 ts0 = *reinterpret_cast<const float4*>(&s_tsh[lb]);
                float4 ts1 = *reinterpret_cast<const float4*>(&s_tsh[lb + 4]);
                float4 st0 = *reinterpret_cast<const float4*>(&s_step[lb]);
                float4 st1 = *reinterpret_cast<const float4*>(&s_step[lb + 4]);
                float tshv[8] = {ts0.x, ts0.y, ts0.z, ts0.w, ts1.x, ts1.y, ts1.z, ts1.w};
                float stv[8]  = {st0.x, st0.y, st0.z, st0.w, st1.x, st1.y, st1.z, st1.w};
#pragma unroll
                for (int i = 0; i < 8; ++i) {
                    float tshl = tshv[i];
                    float x = kt0 - k * tshl;
                    float e = __expf(-x);
                    float s = __fdividef(1.0f, 1.0f + e);
                    float u = wv[i] * stv[i];
                    sumA = fmaf(u, s, sumA);                 // dir/dA = s*step
                    float gg = u * A * s * (1.0f - s);
                    sumG += gg;
                    sumGT = fmaf(gg, tshl, sumGT);
                }
            }
        }

        // ---------- combine partial sums across the two parts ----------
        s_red[p][t0][0] = sumA; s_red[p][t0][1] = sumG; s_red[p][t0][2] = sumGT;
        __syncthreads();
        sumA  += s_red[1 - p][t0][0];   // a+b == b+a bitwise: both parts stay identical
        sumG  += s_red[1 - p][t0][1];
        sumGT += s_red[1 - p][t0][2];

        // full gradients (dc + reg + positivity) and GD update (computed redundantly
        // and identically by both parts)
        float gA = sumA + rlA * (A - pA) + (A  < 0.0f ? 2.0f * A  : 0.0f);
        float gk = fmaf(tz, sumG, -sumGT) + rlk * (k - pk) + (k  < 0.0f ? 2.0f * k  : 0.0f);
        float gt = k * sumG + rlt * (tz - pt) + (tz < 0.0f ? 2.0f * tz : 0.0f);
        A  -= 0.1f * gA;
        k  -= 0.1f * gk;
        tz -= 0.1f * gt;
    }

    if (p == 0) {
        out[v]        = A;
        out[NV + v]   = k;
        out[2*NV + v] = tz;
    }
}

// ---------------- launch ----------------
extern "C" void kernel_launch(void* const* d_in, const int* in_sizes, int n_in,
                              void* d_out, int out_size) {
    const float* ctc   = (const float*)d_in[0];   // (1,128,128,64)
    const float* aif   = (const float*)d_in[1];   // (1,1,1,64)
    const float* time_ = (const float*)d_in[2];   // (64,)
    // d_in[3] = seg (unused by the reference objective)
    const float* eta   = (const float*)d_in[4];   // (1,3,128,128)
    const float* lam   = (const float*)d_in[5];   // (1,)
    float* out = (float*)d_out;                   // (1,3,128,128)

    k_static <<<1, 576>>>(aif, time_);
    k_voxprep<<<64, 256>>>(ctc, eta);
    k_consts <<<1, 64>>>(lam);
    k_main   <<<128, 256>>>(eta, out);
}